// round 7
// baseline (speedup 1.0000x reference)
#include <cuda_runtime.h>
#include <math.h>

#define NT   1000
#define NTP  1024
#define H    128
#define B    1024
#define L    256
#define NTILE 16
#define NPAIR (NTILE*(NTILE+1)/2)   // 136 lower-triangle 64x64 tiles
// W_out (517,3) row-major: rows 0:128 venue, 128:256 team, 256:384 opp,
// 384:512 result, 512 gf, 513 ga, 514:517 stats.

// ---- device scratch ----
__device__ float  g_G[NTP * NTP];
__device__ float4 g_PT1[NTP];
__device__ float4 g_PT2[NTP];
__device__ float4 g_PVR[9];
__device__ float  g_Gven[9];
__device__ float  g_sink;

// ---------------------------------------------------------------------------
// Kernel 1 (fused, grid = 141):
//   blocks 0..135   : symmetric gram tiles + distributed L2 prefetch of the
//                     main kernel's 6 stream arrays (one array per block)
//   blocks 136..139 : team projections
//   block  140      : 3x3 tables + prefetch of next_*/stats
// ---------------------------------------------------------------------------
__global__ void __launch_bounds__(256) prep_gram_kernel(
    const float* __restrict__ E,
    const float* __restrict__ venue_embed,
    const float* __restrict__ result_embed,
    const float* __restrict__ W,
    const float* __restrict__ venue, const float* __restrict__ team,
    const float* __restrict__ opp,   const float* __restrict__ result,
    const float* __restrict__ gf,    const float* __restrict__ ga,
    const float* __restrict__ next_venue, const float* __restrict__ next_team,
    const float* __restrict__ next_opp,   const float* __restrict__ stats) {
    const int bx  = blockIdx.x;
    const int tid = threadIdx.x;

    if (bx < NPAIR) {
        __shared__ float As[64 * 68];
        __shared__ float Bs[64 * 68];
        const int ti = (int)floorf((sqrtf(8.0f * bx + 1.0f) - 1.0f) * 0.5f + 1e-4f);
        const int tj = bx - ti * (ti + 1) / 2;
        const int i0 = ti * 64;
        const int j0 = tj * 64;
        const int tx = tid & 15;
        const int ty = tid >> 4;

        // preload BOTH k-halves of E tiles: 16 LDG.128 in flight
        float4 ra[2][4], rb[2][4];
        const float4 z4 = make_float4(0.f, 0.f, 0.f, 0.f);
        #pragma unroll
        for (int h = 0; h < 2; h++) {
            #pragma unroll
            for (int i = 0; i < 4; i++) {
                const int idx = tid + 256 * i;
                const int t  = idx >> 4;
                const int k4 = idx & 15;
                const int ri = i0 + t;
                const int rj = j0 + t;
                ra[h][i] = (ri < NT) ? *(const float4*)(E + ri * H + 64 * h + 4 * k4) : z4;
                rb[h][i] = (rj < NT) ? *(const float4*)(E + rj * H + 64 * h + 4 * k4) : z4;
            }
        }

        // ---- distributed stream prefetch (rides under gram compute) ----
        // array a = bx % 6, chunk c = bx / 6 (0..22). 2980 float4 per block.
        {
            const float* sa;
            switch (bx % 6) {
                case 0: sa = venue;  break;
                case 1: sa = team;   break;
                case 2: sa = opp;    break;
                case 3: sa = result; break;
                case 4: sa = gf;     break;
                default: sa = ga;    break;
            }
            const int c0 = (bx / 6) * 2980;
            float acc = 0.0f;
            #pragma unroll
            for (int it = 0; it < 12; it++) {
                const int i = c0 + it * 256 + tid;
                if (i < c0 + 2980 && i < (B * L) / 4) {
                    const float4 v = ((const float4*)sa)[i];
                    acc += v.x + v.y + v.z + v.w;
                }
            }
            if (acc == 1.2345e30f) g_sink = acc;
        }

        unsigned long long accp[4][2];
        #pragma unroll
        for (int u = 0; u < 4; u++) { accp[u][0] = 0ull; accp[u][1] = 0ull; }

        #pragma unroll
        for (int h = 0; h < 2; h++) {
            if (h) __syncthreads();
            #pragma unroll
            for (int i = 0; i < 4; i++) {
                const int idx = tid + 256 * i;
                const int t  = idx >> 4;
                const int k4 = idx & 15;
                const int c  = t ^ (4 * (k4 & 7));
                const int r0 = 4 * k4;
                As[(r0 + 0) * 68 + c] = ra[h][i].x;
                As[(r0 + 1) * 68 + c] = ra[h][i].y;
                As[(r0 + 2) * 68 + c] = ra[h][i].z;
                As[(r0 + 3) * 68 + c] = ra[h][i].w;
                Bs[(r0 + 0) * 68 + c] = rb[h][i].x;
                Bs[(r0 + 1) * 68 + c] = rb[h][i].y;
                Bs[(r0 + 2) * 68 + c] = rb[h][i].z;
                Bs[(r0 + 3) * 68 + c] = rb[h][i].w;
            }
            __syncthreads();

            #pragma unroll 16
            for (int k = 0; k < 64; k++) {
                const int cc = (k >> 2) & 7;
                const float4 a4 = *(const float4*)&As[k * 68 + 4 * (ty ^ cc)];
                const ulonglong2 b2 = *(const ulonglong2*)&Bs[k * 68 + 4 * (tx ^ cc)];
                const unsigned int au[4] = {
                    __float_as_uint(a4.x), __float_as_uint(a4.y),
                    __float_as_uint(a4.z), __float_as_uint(a4.w)};
                #pragma unroll
                for (int u = 0; u < 4; u++) {
                    unsigned long long ap;
                    asm("mov.b64 %0, {%1, %1};" : "=l"(ap) : "r"(au[u]));
                    asm("fma.rn.f32x2 %0, %1, %2, %0;"
                        : "+l"(accp[u][0]) : "l"(ap), "l"(b2.x));
                    asm("fma.rn.f32x2 %0, %1, %2, %0;"
                        : "+l"(accp[u][1]) : "l"(ap), "l"(b2.y));
                }
            }
        }

        float acc[4][4];
        #pragma unroll
        for (int u = 0; u < 4; u++) {
            unsigned int lo, hi;
            asm("mov.b64 {%0, %1}, %2;" : "=r"(lo), "=r"(hi) : "l"(accp[u][0]));
            acc[u][0] = __uint_as_float(lo); acc[u][1] = __uint_as_float(hi);
            asm("mov.b64 {%0, %1}, %2;" : "=r"(lo), "=r"(hi) : "l"(accp[u][1]));
            acc[u][2] = __uint_as_float(lo); acc[u][3] = __uint_as_float(hi);
        }

        float4* G4 = (float4*)g_G;
        #pragma unroll
        for (int u = 0; u < 4; u++) {
            const int i = i0 + 4 * ty + u;
            G4[(i * NTP + j0) / 4 + tx] =
                make_float4(acc[u][0], acc[u][1], acc[u][2], acc[u][3]);
        }
        if (ti != tj) {
            #pragma unroll
            for (int v = 0; v < 4; v++) {
                const int j = j0 + 4 * tx + v;
                G4[(j * NTP + i0) / 4 + ty] =
                    make_float4(acc[0][v], acc[1][v], acc[2][v], acc[3][v]);
            }
        }
        return;
    }

    if (bx < NPAIR + 4) {
        const int t = (bx - NPAIR) * 256 + tid;
        if (t < NT) {
            const float4* row = (const float4*)(E + t * H);
            float a0 = 0, a1 = 0, a2 = 0, b0 = 0, b1 = 0, b2 = 0;
            #pragma unroll 8
            for (int k4 = 0; k4 < 32; k4++) {
                const float4 e = row[k4];
                const float ev[4] = {e.x, e.y, e.z, e.w};
                #pragma unroll
                for (int d = 0; d < 4; d++) {
                    const int k = 4 * k4 + d;
                    a0 += ev[d] * W[(128 + k) * 3 + 0];
                    a1 += ev[d] * W[(128 + k) * 3 + 1];
                    a2 += ev[d] * W[(128 + k) * 3 + 2];
                    b0 += ev[d] * W[(256 + k) * 3 + 0];
                    b1 += ev[d] * W[(256 + k) * 3 + 1];
                    b2 += ev[d] * W[(256 + k) * 3 + 2];
                }
            }
            g_PT1[t] = make_float4(a0, a1, a2, 0.0f);
            g_PT2[t] = make_float4(b0, b1, b2, 0.0f);
        }
        return;
    }

    // 3x3 tables + small-array prefetch
    {
        const int w    = tid >> 5;
        const int lane = tid & 31;
        // prefetch next_*/stats into L2
        {
            float acc = 0.0f;
            if (tid < B / 4) {
                const float4 a = ((const float4*)next_venue)[tid];
                const float4 b = ((const float4*)next_team)[tid];
                const float4 c = ((const float4*)next_opp)[tid];
                acc += a.x + b.x + c.x;
            }
            const int sidx = tid + 256;   // stats: 3072 floats = 768 float4
            if (sidx < 768 + 256) {
                acc += ((const float4*)stats)[sidx - 256].x;
            }
            if (tid < 256) {
                acc += ((const float4*)stats)[tid].x
                     + ((const float4*)stats)[tid + 512].x;
            }
            if (acc == 1.2345e30f) g_sink = acc;
        }
        for (int p = w; p < 9; p += 8) {
            const int i = p / 3, j = p % 3;
            const float4 vi = *(const float4*)(venue_embed  + i * H + 4 * lane);
            const float4 vj = *(const float4*)(venue_embed  + j * H + 4 * lane);
            const float4 re = *(const float4*)(result_embed + j * H + 4 * lane);
            const float4 w0 = *(const float4*)(W + 12 * lane + 0);
            const float4 w1 = *(const float4*)(W + 12 * lane + 4);
            const float4 w2 = *(const float4*)(W + 12 * lane + 8);
            const float4 q0 = *(const float4*)(W + 384 * 3 + 12 * lane + 0);
            const float4 q1 = *(const float4*)(W + 384 * 3 + 12 * lane + 4);
            const float4 q2 = *(const float4*)(W + 384 * 3 + 12 * lane + 8);
            const float viv[4] = {vi.x, vi.y, vi.z, vi.w};
            const float vjv[4] = {vj.x, vj.y, vj.z, vj.w};
            const float rev[4] = {re.x, re.y, re.z, re.w};
            const float wv[12] = {w0.x, w0.y, w0.z, w0.w, w1.x, w1.y, w1.z, w1.w,
                                  w2.x, w2.y, w2.z, w2.w};
            const float qv[12] = {q0.x, q0.y, q0.z, q0.w, q1.x, q1.y, q1.z, q1.w,
                                  q2.x, q2.y, q2.z, q2.w};
            float gv = 0, p0 = 0, p1 = 0, p2 = 0;
            #pragma unroll
            for (int d = 0; d < 4; d++) {
                gv += viv[d] * vjv[d];
                p0 += viv[d] * wv[3 * d + 0] + rev[d] * qv[3 * d + 0];
                p1 += viv[d] * wv[3 * d + 1] + rev[d] * qv[3 * d + 1];
                p2 += viv[d] * wv[3 * d + 2] + rev[d] * qv[3 * d + 2];
            }
            #pragma unroll
            for (int off = 16; off; off >>= 1) {
                gv += __shfl_xor_sync(0xffffffffu, gv, off);
                p0 += __shfl_xor_sync(0xffffffffu, p0, off);
                p1 += __shfl_xor_sync(0xffffffffu, p1, off);
                p2 += __shfl_xor_sync(0xffffffffu, p2, off);
            }
            if (lane == 0) {
                g_Gven[p] = gv;
                g_PVR[p]  = make_float4(p0, p1, p2, 0.0f);
            }
        }
    }
}

// ---------------------------------------------------------------------------
// Kernel 2: main — 2 warps per batch, 4 batches per 256-thread block, grid 256.
// Dynamic smem (floats):
//   [0, 8192)        rows[4][2][1024]   (batch q: nt row, no row)
//   [8192, 12288)    PT1s (1024 float4)
//   [12288, 16384)   PT2s (1024 float4)
//   [16384, 16420)   PVRs (9 float4)
//   [16420, 16429)   Gvens (9 float)
// ---------------------------------------------------------------------------
#define MAIN_SMEM_BYTES (16432 * 4)

__global__ void __launch_bounds__(256) main_kernel(
    const int* __restrict__ venue, const int* __restrict__ team,
    const int* __restrict__ opp,   const int* __restrict__ result,
    const float* __restrict__ gf,  const float* __restrict__ ga,
    const float* __restrict__ stats,
    const int* __restrict__ next_venue, const int* __restrict__ next_team,
    const int* __restrict__ next_opp,
    const float* __restrict__ W, const float* __restrict__ b_out,
    float* __restrict__ out) {

    extern __shared__ float sm[];
    float*  rows  = sm;
    float4* PT1s  = (float4*)(sm + 8192);
    float4* PT2s  = (float4*)(sm + 12288);
    float4* PVRs  = (float4*)(sm + 16384);
    float*  Gvens = sm + 16420;

    __shared__ float red_m[8];
    __shared__ float red_s[8];
    __shared__ float red_c[8][3];

    const int tid  = threadIdx.x;
    const int lane = tid & 31;
    const int w    = tid >> 5;
    const int q    = w >> 1;           // batch slot 0..3
    const int half = w & 1;
    const int b    = blockIdx.x * 4 + q;

    // ---- stream loads first (independent, L2 after prefetch) ----
    const int idx0 = b * L + half * 128 + lane * 4;
    const int4   v4  = *(const int4*)(venue  + idx0);
    const int4   t4  = *(const int4*)(team   + idx0);
    const int4   o4  = *(const int4*)(opp    + idx0);
    const int4   r4  = *(const int4*)(result + idx0);
    const float4 gf4 = *(const float4*)(gf + idx0);
    const float4 ga4 = *(const float4*)(ga + idx0);

    const int nv = next_venue[b];
    const int nt = next_team[b];
    const int no = next_opp[b];

    // ---- stage this batch's Gram row: half 0 -> nt row, half 1 -> no row ----
    {
        const int trow = half ? no : nt;
        const float4* src = (const float4*)(g_G + trow * NTP);
        float4* dst = (float4*)(rows + q * 2048 + half * 1024);
        #pragma unroll
        for (int i = 0; i < 8; i++)
            dst[lane + 32 * i] = src[lane + 32 * i];
    }
    // ---- stage tables (block-cooperative) ----
    #pragma unroll
    for (int i = 0; i < 4; i++) {
        PT1s[tid + 256 * i] = g_PT1[tid + 256 * i];
        PT2s[tid + 256 * i] = g_PT2[tid + 256 * i];
    }
    if (tid < 9) { PVRs[tid] = g_PVR[tid]; Gvens[tid] = g_Gven[tid]; }

    const int   vv[4]  = {v4.x, v4.y, v4.z, v4.w};
    const int   tt[4]  = {t4.x, t4.y, t4.z, t4.w};
    const int   oo[4]  = {o4.x, o4.y, o4.z, o4.w};
    const int   rr[4]  = {r4.x, r4.y, r4.z, r4.w};
    const float gfv[4] = {gf4.x, gf4.y, gf4.z, gf4.w};
    const float gav[4] = {ga4.x, ga4.y, ga4.z, ga4.w};

    __syncthreads();

    const float* rw0 = rows + q * 2048;          // nt row
    const float* rw1 = rows + q * 2048 + 1024;   // no row

    const float inv_scale = 0.051031036307982884f;  // 1/sqrt(384)
    float s[4];
    #pragma unroll
    for (int j = 0; j < 4; j++)
        s[j] = (Gvens[vv[j] * 3 + nv] + rw0[tt[j]] + rw1[oo[j]]) * inv_scale;

    // cross-warp softmax (2 warps per batch)
    float m = fmaxf(fmaxf(s[0], s[1]), fmaxf(s[2], s[3]));
    #pragma unroll
    for (int off = 16; off; off >>= 1)
        m = fmaxf(m, __shfl_xor_sync(0xffffffffu, m, off));
    if (lane == 0) red_m[w] = m;
    __syncthreads();
    m = fmaxf(red_m[w], red_m[w ^ 1]);

    float e[4], su = 0.0f;
    #pragma unroll
    for (int j = 0; j < 4; j++) { e[j] = __expf(s[j] - m); su += e[j]; }
    #pragma unroll
    for (int off = 16; off; off >>= 1)
        su += __shfl_xor_sync(0xffffffffu, su, off);
    if (lane == 0) red_s[w] = su;
    __syncthreads();
    const float inv = __frcp_rn(red_s[w] + red_s[w ^ 1]);

    const float wgf0 = W[512 * 3 + 0], wgf1 = W[512 * 3 + 1], wgf2 = W[512 * 3 + 2];
    const float wga0 = W[513 * 3 + 0], wga1 = W[513 * 3 + 1], wga2 = W[513 * 3 + 2];

    float c0 = 0, c1 = 0, c2 = 0;
    #pragma unroll
    for (int j = 0; j < 4; j++) {
        const float a = e[j] * inv;
        const float4 p1  = PT1s[tt[j]];
        const float4 p2  = PT2s[oo[j]];
        const float4 pvr = PVRs[vv[j] * 3 + rr[j]];
        c0 += a * (p1.x + p2.x + pvr.x + gfv[j] * wgf0 + gav[j] * wga0);
        c1 += a * (p1.y + p2.y + pvr.y + gfv[j] * wgf1 + gav[j] * wga1);
        c2 += a * (p1.z + p2.z + pvr.z + gfv[j] * wgf2 + gav[j] * wga2);
    }
    #pragma unroll
    for (int off = 16; off; off >>= 1) {
        c0 += __shfl_xor_sync(0xffffffffu, c0, off);
        c1 += __shfl_xor_sync(0xffffffffu, c1, off);
        c2 += __shfl_xor_sync(0xffffffffu, c2, off);
    }
    if (lane == 0) { red_c[w][0] = c0; red_c[w][1] = c1; red_c[w][2] = c2; }
    __syncthreads();

    if (half == 0 && lane == 0) {
        c0 = red_c[w][0] + red_c[w + 1][0];
        c1 = red_c[w][1] + red_c[w + 1][1];
        c2 = red_c[w][2] + red_c[w + 1][2];
        const float s0 = stats[b * 3 + 0], s1 = stats[b * 3 + 1], s2 = stats[b * 3 + 2];
        c0 += s0 * W[514 * 3 + 0] + s1 * W[515 * 3 + 0] + s2 * W[516 * 3 + 0] + b_out[0];
        c1 += s0 * W[514 * 3 + 1] + s1 * W[515 * 3 + 1] + s2 * W[516 * 3 + 1] + b_out[1];
        c2 += s0 * W[514 * 3 + 2] + s1 * W[515 * 3 + 2] + s2 * W[516 * 3 + 2] + b_out[2];
        out[b * 3 + 0] = c0;
        out[b * 3 + 1] = c1;
        out[b * 3 + 2] = c2;
    }
}

// ---------------------------------------------------------------------------
extern "C" void kernel_launch(void* const* d_in, const int* in_sizes, int n_in,
                              void* d_out, int out_size) {
    const float* team_embed    = (const float*)d_in[0];
    const float* venue_embed   = (const float*)d_in[1];
    const float* result_embed  = (const float*)d_in[2];
    const float* W_out         = (const float*)d_in[3];
    const float* b_out         = (const float*)d_in[4];
    const float* goals_for     = (const float*)d_in[5];
    const float* goals_against = (const float*)d_in[6];
    const float* stats         = (const float*)d_in[7];
    const int*   venue         = (const int*)d_in[8];
    const int*   team          = (const int*)d_in[9];
    const int*   opponent      = (const int*)d_in[10];
    const int*   result        = (const int*)d_in[11];
    const int*   next_venue    = (const int*)d_in[12];
    const int*   next_team     = (const int*)d_in[13];
    const int*   next_opponent = (const int*)d_in[14];
    float* out = (float*)d_out;

    cudaFuncSetAttribute(main_kernel,
                         cudaFuncAttributeMaxDynamicSharedMemorySize,
                         MAIN_SMEM_BYTES);

    prep_gram_kernel<<<NPAIR + 5, 256>>>(
        team_embed, venue_embed, result_embed, W_out,
        (const float*)venue, (const float*)team,
        (const float*)opponent, (const float*)result,
        goals_for, goals_against,
        (const float*)next_venue, (const float*)next_team,
        (const float*)next_opponent, stats);

    main_kernel<<<256, 256, MAIN_SMEM_BYTES>>>(
        venue, team, opponent, result,
        goals_for, goals_against, stats,
        next_venue, next_team, next_opponent,
        W_out, b_out, out);
}